// round 1
// baseline (speedup 1.0000x reference)
#include <cuda_runtime.h>
#include <cstdint>

#define HW 50176           // 224*224
#define S_BANDS 371
#define OUT_ELEMS (3*HW)   // 150528

// 2*pi*H*C*1e9 * STRESS_MAGNITUDE  (phase = coef * norm_stress / lambda_nm)
// 2*pi*0.01*3.5e-12*1e9*7.2e7 = 15833.62697...
#define PHASE_SCALE 15833.626974092555

static __device__ float    g_min_s;
static __device__ float    g_scale;       // PHASE_SCALE / (max - min)
static __device__ float    g_wsum[3];     // sum_s 0.5*ss[s][c]
static __device__ unsigned g_isomax_bits; // atomicMax on float bits (iso >= 0)

// ---------------------------------------------------------------------------
// Kernel 1: single block. min/max of stressmap, weight-channel sums, reset max.
// ---------------------------------------------------------------------------
__global__ void __launch_bounds__(1024) prep_kernel(const float* __restrict__ sm,
                                                    const float* __restrict__ ss) {
    __shared__ float smn[32], smx[32];
    const int tid = threadIdx.x;

    float mn = 3.4e38f, mx = -3.4e38f;
    const float4* s4 = (const float4*)sm;
    #pragma unroll 4
    for (int i = tid; i < HW / 4; i += 1024) {
        float4 v = s4[i];
        mn = fminf(mn, fminf(fminf(v.x, v.y), fminf(v.z, v.w)));
        mx = fmaxf(mx, fmaxf(fmaxf(v.x, v.y), fmaxf(v.z, v.w)));
    }
    #pragma unroll
    for (int o = 16; o; o >>= 1) {
        mn = fminf(mn, __shfl_xor_sync(0xFFFFFFFFu, mn, o));
        mx = fmaxf(mx, __shfl_xor_sync(0xFFFFFFFFu, mx, o));
    }
    if ((tid & 31) == 0) { smn[tid >> 5] = mn; smx[tid >> 5] = mx; }

    // Warp 1 computes the per-channel weight sums (independent of the barrier).
    if (tid >= 32 && tid < 64) {
        int l = tid - 32;
        float w0 = 0.f, w1 = 0.f, w2 = 0.f;
        for (int s = l; s < S_BANDS; s += 32) {
            w0 += ss[3 * s + 0];
            w1 += ss[3 * s + 1];
            w2 += ss[3 * s + 2];
        }
        #pragma unroll
        for (int o = 16; o; o >>= 1) {
            w0 += __shfl_xor_sync(0xFFFFFFFFu, w0, o);
            w1 += __shfl_xor_sync(0xFFFFFFFFu, w1, o);
            w2 += __shfl_xor_sync(0xFFFFFFFFu, w2, o);
        }
        if (l == 0) {
            g_wsum[0] = 0.5f * w0;
            g_wsum[1] = 0.5f * w1;
            g_wsum[2] = 0.5f * w2;
        }
    }

    __syncthreads();
    if (tid < 32) {
        mn = smn[tid]; mx = smx[tid];
        #pragma unroll
        for (int o = 16; o; o >>= 1) {
            mn = fminf(mn, __shfl_xor_sync(0xFFFFFFFFu, mn, o));
            mx = fmaxf(mx, __shfl_xor_sync(0xFFFFFFFFu, mx, o));
        }
        if (tid == 0) {
            g_min_s = mn;
            g_scale = (float)(PHASE_SCALE / (double)(mx - mn));
            g_isomax_bits = 0u;
        }
    }
}

// ---------------------------------------------------------------------------
// Kernel 2: main compute. One thread per pixel; 371-band loop.
// iso_c = Wsum_c - sum_s w_sc * cos(t * q_s).  Writes unnormalized iso to out
// in channel-major layout and atomically tracks the global max.
// ---------------------------------------------------------------------------
__global__ void __launch_bounds__(256) fringe_kernel(const float* __restrict__ sm,
                                                     const float* __restrict__ ss,
                                                     float* __restrict__ out) {
    __shared__ float4 tab[S_BANDS];   // {1/lambda, w0, w1, w2}
    const int tid = threadIdx.x;

    for (int s = tid; s < S_BANDS; s += 256) {
        float lam = 390.0f + (float)s;
        tab[s] = make_float4(1.0f / lam,
                             0.5f * ss[3 * s + 0],
                             0.5f * ss[3 * s + 1],
                             0.5f * ss[3 * s + 2]);
    }
    __syncthreads();

    const int p = blockIdx.x * 256 + tid;
    const float t = (sm[p] - g_min_s) * g_scale;

    float a0 = 0.f, a1 = 0.f, a2 = 0.f;
    #pragma unroll 7
    for (int s = 0; s < S_BANDS; s++) {
        float4 v = tab[s];
        float c = __cosf(t * v.x);          // single MUFU.COS
        a0 = fmaf(v.y, c, a0);
        a1 = fmaf(v.z, c, a1);
        a2 = fmaf(v.w, c, a2);
    }

    const float i0 = g_wsum[0] - a0;
    const float i1 = g_wsum[1] - a1;
    const float i2 = g_wsum[2] - a2;

    out[p]          = i0;
    out[HW + p]     = i1;
    out[2 * HW + p] = i2;

    float m = fmaxf(i0, fmaxf(i1, i2));
    #pragma unroll
    for (int o = 16; o; o >>= 1) m = fmaxf(m, __shfl_xor_sync(0xFFFFFFFFu, m, o));
    if ((tid & 31) == 0) atomicMax(&g_isomax_bits, __float_as_uint(m));
}

// ---------------------------------------------------------------------------
// Kernel 3: normalize in place (float4).
// ---------------------------------------------------------------------------
__global__ void __launch_bounds__(256) norm_kernel(float* __restrict__ out) {
    const int i = blockIdx.x * 256 + threadIdx.x;
    const float inv = 1.0f / __uint_as_float(g_isomax_bits);
    if (i < OUT_ELEMS / 4) {
        float4 v = ((float4*)out)[i];
        v.x *= inv; v.y *= inv; v.z *= inv; v.w *= inv;
        ((float4*)out)[i] = v;
    }
}

extern "C" void kernel_launch(void* const* d_in, const int* in_sizes, int n_in,
                              void* d_out, int out_size) {
    const float* sm = (const float*)d_in[0];
    const float* ss = (const float*)d_in[1];
    if (in_sizes[0] != HW) {  // defensive: identify by element count
        sm = (const float*)d_in[1];
        ss = (const float*)d_in[0];
    }
    float* out = (float*)d_out;

    prep_kernel<<<1, 1024>>>(sm, ss);
    fringe_kernel<<<HW / 256, 256>>>(sm, ss, out);           // 196 blocks
    norm_kernel<<<(OUT_ELEMS / 4 + 255) / 256, 256>>>(out);  // 147 blocks
}